// round 11
// baseline (speedup 1.0000x reference)
#include <cuda_runtime.h>
#include <math.h>
#include <stdint.h>

#define NB 8
#define NH 16
#define ND 64
#define NS 1024
#define NE 1024
#define PADP 68   // row stride: 68 % 32 == 4 -> conflict-free row-set accesses

// ---------------- scratch ----------------
__device__ float g_pe[NH*ND*NS];     // (h,d,s) positional encoding
__device__ float g_xh[NH*NB*NS*ND];  // (h,b,s,d) pos-encoded input (residual), fp32
__device__ float g_q [NH*NB*NS*ND];  // A-frag layout per 128-row tile, scale folded
__device__ float g_k [NH*NB*NS*ND];  // B-frag layout per 64-row chunk
__device__ float g_v [NH*NB*NS*ND];  // B-frag (V role) layout per 64-row chunk
__device__ float g_y [NB*NE*NS];     // (b,e,s) pre-layernorm
__device__ float g_psum[NH*NB*NS];   // per-head partial sum of y over its 64 dims
__device__ float g_psq [NH*NB*NS];   // per-head partial sum of y^2
__device__ float g_mu[NB*NS];        // layernorm mean
__device__ float g_rs[NB*NS];        // layernorm rsqrt(var+eps)

// ---------------- helpers ----------------
__device__ __forceinline__ float ftanh(float x) {
    const float e = __expf(2.0f * x);
    return 1.0f - __fdividef(2.0f, e + 1.0f);
}
__device__ __forceinline__ void mma8(float* c, const float* a, const float* b) {
    asm volatile(
        "mma.sync.aligned.m16n8k8.row.col.f32.tf32.tf32.f32 "
        "{%0,%1,%2,%3}, {%4,%5,%6,%7}, {%8,%9}, {%0,%1,%2,%3};\n"
        : "+f"(c[0]), "+f"(c[1]), "+f"(c[2]), "+f"(c[3])
        : "r"(__float_as_uint(a[0])), "r"(__float_as_uint(a[1])),
          "r"(__float_as_uint(a[2])), "r"(__float_as_uint(a[3])),
          "r"(__float_as_uint(b[0])), "r"(__float_as_uint(b[1])));
}
__device__ __forceinline__ uint32_t su(const void* p) {
    return (uint32_t)__cvta_generic_to_shared(p);
}
__device__ __forceinline__ void cp16(uint32_t s, const void* g) {
    asm volatile("cp.async.cg.shared.global [%0], [%1], 16;\n" :: "r"(s), "l"(g));
}
__device__ __forceinline__ void cp4(uint32_t s, const void* g) {
    asm volatile("cp.async.ca.shared.global [%0], [%1], 4;\n" :: "r"(s), "l"(g));
}
#define CP_COMMIT asm volatile("cp.async.commit_group;\n" ::: "memory")
#define CP_WAIT0  asm volatile("cp.async.wait_group 0;\n" ::: "memory")
#define PAIR_BAR(rw) asm volatile("bar.sync %0, 64;" :: "r"((rw)+1) : "memory")

// ---------------- kernel 0: positional encoding table, (h,d,s) layout ------------
__global__ __launch_bounds__(256) void k_pe()
{
    const int idx = blockIdx.x*256 + threadIdx.x;   // over NH*(ND/2)*NS
    const int h = idx >> 15;
    const int m = (idx >> 10) & 31;
    const int s = idx & 1023;
    const int l = h*64 + (s >> 4);
    const int eh = ((s & 15) << 5) | m;
    const float freq = __expf((float)eh * (-2.0f*9.210340371976184f/1024.0f));
    float sv, cv;
    sincosf((float)l * freq, &sv, &cv);
    const int base = h*65536 + (m << 11) + s;
    g_pe[base]        = sv;
    g_pe[base + 1024] = cv;
}

// ---------------- kernel 1: posenc-add + QKV MLPs (64-row tiles, 3 CTAs/SM) ------
// warp = (rw = wid&3 row-group, nh = wid>>2 nt-half); pair {rw, rw+4} shares rows.
// smem: sX[64*68] | sZ[64*68] | sWf0[4096] | sWf1[4096] = 67.6KB
#define SMEM1_FLOATS (64*PADP + 64*PADP + 4096 + 4096)

__device__ __forceinline__ void wfetch(uint32_t dstu, const float* __restrict__ W, int tid)
{
    #pragma unroll
    for (int i = 0; i < 16; ++i) {
        const int fi = tid + i*256;
        const int hi = fi & 1, ln = (fi >> 1) & 31, ks = (fi >> 6) & 7, nt = fi >> 9;
        const int g8 = ln >> 2, tt = ln & 3;
        cp4(dstu + fi*4, W + (ks*8 + tt + 4*hi)*64 + nt*8 + g8);
    }
}

// one MLP layer: A scalar from src rows rA (64-row tile), nt-half per warp -> dst
template<bool FIRST>
__device__ __forceinline__ void qkv_layer(const float* __restrict__ src,
                                          float* __restrict__ dst,
                                          const float* __restrict__ sWf,
                                          const float* __restrict__ biasg,
                                          int rw, int nh, int lane, int gid, int t4)
{
    const int rA = rw*16 + gid;
    float cc[4][4];
    #pragma unroll
    for (int nt = 0; nt < 4; ++nt) { cc[nt][0]=cc[nt][1]=cc[nt][2]=cc[nt][3]=0.f; }
    #pragma unroll
    for (int ks = 0; ks < 8; ++ks) {
        const int ac = ks*8 + t4;
        float a[4];
        a[0] = src[rA*PADP + ac];
        a[1] = src[(rA+8)*PADP + ac];
        a[2] = src[rA*PADP + ac + 4];
        a[3] = src[(rA+8)*PADP + ac + 4];
        #pragma unroll
        for (int nt = 0; nt < 4; ++nt) {
            const float2 bb = *(const float2*)&sWf[(((nh*4+nt)*8+ks)*32 + lane)*2];
            mma8(cc[nt], a, (const float*)&bb);
        }
    }
    if (!FIRST) PAIR_BAR(rw);   // in-place layer: pair done reading rows before overwrite
    #pragma unroll
    for (int nt = 0; nt < 4; ++nt) {
        const int col = (nh*4+nt)*8 + t4*2;
        const float2 bv = *(const float2*)&biasg[col];
        #pragma unroll
        for (int r = 0; r < 2; ++r) {
            const int row = rA + 8*r;
            *(float2*)&dst[row*PADP + col] =
                make_float2(ftanh(cc[nt][2*r] + bv.x), ftanh(cc[nt][2*r+1] + bv.y));
        }
    }
    if (FIRST) PAIR_BAR(rw);    // pair wrote both col halves of rows rA before l2 reads
}

__global__ __launch_bounds__(256, 3) void k_qkv(
    const float* __restrict__ x,
    const float* __restrict__ Wq1, const float* __restrict__ bq1,
    const float* __restrict__ Wq2, const float* __restrict__ bq2,
    const float* __restrict__ Wk1, const float* __restrict__ bk1,
    const float* __restrict__ Wk2, const float* __restrict__ bk2,
    const float* __restrict__ Wv1, const float* __restrict__ bv1,
    const float* __restrict__ Wv2, const float* __restrict__ bv2)
{
    extern __shared__ float sm[];
    float* sX   = sm;                        // [64*68] xh (read-only after build)
    float* sZ   = sX + 64*PADP;              // [64*68] layer activations
    float* sWfA = sZ + 64*PADP;              // [4096]
    float* sWfB = sWfA + 4096;               // [4096]

    const int tid = threadIdx.x;
    const int lane = tid & 31, wid = tid >> 5;
    const int gid = lane >> 2, t4 = lane & 3;
    const int rw = wid & 3, nh = wid >> 2;
    const int h = blockIdx.z, b = blockIdx.y, bx = blockIdx.x;
    const int s0 = bx * 64;
    const int hb = h*NB + b;

    const float* Wl[6] = {Wq1, Wq2, Wk1, Wk2, Wv1, Wv2};
    const float* Bl[6] = {bq1, bq2, bk1, bk2, bv1, bv2};

    // prefetch W0 into frag layout; overlaps xh build below
    wfetch(su(sWfA), Wl[0] + h*4096, tid);
    CP_COMMIT;

    // xh = x + pe (table lookup) -> sX
    for (int idx = tid; idx < 64*64; idx += 256) {
        const int d = idx >> 6, si = idx & 63;
        const int s = s0 + si;
        sX[si*PADP + d] = x[(b*NE + (h*64 + d))*NS + s] + g_pe[h*65536 + (d << 10) + s];
    }
    __syncthreads();
    {   // persist residual copy
        float* dst = g_xh + (hb*NS + s0)*ND;
        for (int idx = tid; idx < 64*16; idx += 256) {
            const int si = idx >> 4, d4 = (idx & 15) * 4;
            *(float4*)(dst + si*64 + d4) = *(float4*)&sX[si*PADP + d4];
        }
    }
    CP_WAIT0;
    __syncthreads();   // W0 visible; sX complete

    float* cur = sWfA;
    float* nxt = sWfB;

    #pragma unroll 1
    for (int l = 0; l < 6; ++l) {
        if (l < 5) { wfetch(su(nxt), Wl[l+1] + h*4096, tid); CP_COMMIT; }
        if ((l & 1) == 0) {
            qkv_layer<true>(sX, sZ, cur, Bl[l] + h*64, rw, nh, lane, gid, t4);
        } else {
            qkv_layer<false>(sZ, sZ, cur, Bl[l] + h*64, rw, nh, lane, gid, t4);
            __syncthreads();   // sZ final before block-wide permute reads
            const int p = l >> 1;
            if (p == 0) {          // Q: A-frag within its 128-row tile, scale folded
                float* qb = g_q + (hb*8 + (bx >> 1))*8192;
                const int wbase = (bx & 1)*4;
                for (int fi = tid; fi < 4096; fi += 256) {
                    const int wl = fi >> 10, rest = fi & 1023;
                    const int rhi = rest & 3, r = rhi & 1, hi = rhi >> 1;
                    const int ln = (rest >> 2) & 31, g8 = ln >> 2, tt = ln & 3;
                    const int ks = (rest >> 7) & 7;
                    qb[(wbase + wl)*1024 + rest] =
                        0.03125f * sZ[(wl*16 + g8 + 8*r)*PADP + ks*8 + tt + 4*hi];
                }
            } else if (p == 1) {   // K: B-frag chunk (this block == chunk bx)
                float* kb = g_k + (hb*16 + bx)*4096;
                for (int f = tid; f < 4096; f += 256) {
                    const int hi = f & 1;
                    const int ln = (f >> 1) & 31, g8 = ln >> 2, tt = ln & 3;
                    const int ks = (f >> 6) & 7, nt = f >> 9;
                    kb[f] = sZ[(nt*8 + g8)*PADP + ks*8 + tt + 4*hi];
                }
            } else {               // V: k=j, n=d frag chunk
                float* vb = g_v + (hb*16 + bx)*4096;
                for (int f = tid; f < 4096; f += 256) {
                    const int hi = f & 1;
                    const int ln = (f >> 1) & 31, g8 = ln >> 2, tt = ln & 3;
                    const int dt = (f >> 6) & 7, ksv = f >> 9;
                    vb[f] = sZ[(ksv*8 + 4*hi + tt)*PADP + dt*8 + g8];
                }
            }
        }
        if (l < 5) { CP_WAIT0; }
        __syncthreads();   // next W visible; sZ free for reuse
        float* t = cur; cur = nxt; nxt = t;
    }
}

// ---------------- kernel 2: flash attention + residual + LN partial stats ----------
// smem: sQf[8192] | buf0 K/V [8192] | buf1 K/V [8192] = 96KB
#define SMEM2_FLOATS (8192 + 8192 + 8192)

__global__ __launch_bounds__(256, 2) void k_attn()
{
    extern __shared__ float sm[];
    float* sQf  = sm;
    float* buf0 = sm + 8192;
    float* buf1 = sm + 16384;
    const uint32_t b0u = su(buf0), b1u = su(buf1), qfu = su(sQf);

    const int tid = threadIdx.x;
    const int lane = tid & 31, wid = tid >> 5;
    const int gid = lane >> 2, t4 = lane & 3;
    const int rA = wid*16 + gid;

    const int h = blockIdx.z, b = blockIdx.y, bx = blockIdx.x;
    const int hb = h*NB + b;
    const float* qt = g_q + (hb*8 + bx)*8192;
    const float* kb = g_k + hb*16*4096;
    const float* vb = g_v + hb*16*4096;

    #pragma unroll
    for (int i = 0; i < 8; ++i)
        cp16(qfu + (tid + i*256)*16, qt + (tid + i*256)*4);
    #pragma unroll
    for (int i = 0; i < 4; ++i) {
        cp16(b0u + (tid + i*256)*16,         kb + (tid + i*256)*4);
        cp16(b0u + 16384 + (tid + i*256)*16, vb + (tid + i*256)*4);
    }
    CP_COMMIT;

    float l2[2] = {0.f, 0.f};
    float o[8][4];
    #pragma unroll
    for (int nt = 0; nt < 8; ++nt) { o[nt][0]=o[nt][1]=o[nt][2]=o[nt][3]=0.f; }

    const int qsrc1 = (lane & ~3) | (t4 >> 1);
    const int qsrc2 = qsrc1 + 2;
    const bool osel = (t4 & 1);

    #pragma unroll 1
    for (int kt = 0; kt < 16; ++kt) {
        CP_WAIT0;
        __syncthreads();
        if (kt < 15) {
            const uint32_t bu = ((kt+1) & 1) ? b1u : b0u;
            const float* ksrc = kb + (kt+1)*4096;
            const float* vsrc = vb + (kt+1)*4096;
            #pragma unroll
            for (int i = 0; i < 4; ++i) {
                cp16(bu + (tid + i*256)*16,         ksrc + (tid + i*256)*4);
                cp16(bu + 16384 + (tid + i*256)*16, vsrc + (tid + i*256)*4);
            }
            CP_COMMIT;
        }
        const float* Kf = (kt & 1) ? buf1 : buf0;
        const float* Vf = Kf + 4096;

        float sc[8][4];
        #pragma unroll
        for (int nt = 0; nt < 8; ++nt) { sc[nt][0]=sc[nt][1]=sc[nt][2]=sc[nt][3]=0.f; }
        #pragma unroll
        for (int ks = 0; ks < 8; ++ks) {
            const float4 av = *(const float4*)&sQf[((wid*8+ks)*32 + lane)*4];
            #pragma unroll
            for (int nt = 0; nt < 8; ++nt) {
                const float2 bb = *(const float2*)&Kf[((nt*8+ks)*32 + lane)*2];
                mma8(sc[nt], (const float*)&av, (const float*)&bb);
            }
        }

        #pragma unroll
        for (int nt = 0; nt < 8; ++nt) {
            sc[nt][0] = __expf(sc[nt][0]);
            sc[nt][1] = __expf(sc[nt][1]);
            sc[nt][2] = __expf(sc[nt][2]);
            sc[nt][3] = __expf(sc[nt][3]);
            l2[0] += sc[nt][0] + sc[nt][1];
            l2[1] += sc[nt][2] + sc[nt][3];
        }

        #pragma unroll
        for (int ks = 0; ks < 8; ++ks) {
            const float x0 = __shfl_sync(0xffffffffu, sc[ks][0], qsrc1);
            const float x1 = __shfl_sync(0xffffffffu, sc[ks][1], qsrc1);
            const float x2 = __shfl_sync(0xffffffffu, sc[ks][2], qsrc1);
            const float x3 = __shfl_sync(0xffffffffu, sc[ks][3], qsrc1);
            const float y0 = __shfl_sync(0xffffffffu, sc[ks][0], qsrc2);
            const float y1 = __shfl_sync(0xffffffffu, sc[ks][1], qsrc2);
            const float y2 = __shfl_sync(0xffffffffu, sc[ks][2], qsrc2);
            const float y3 = __shfl_sync(0xffffffffu, sc[ks][3], qsrc2);
            float a[4];
            a[0] = osel ? x1 : x0;
            a[1] = osel ? x3 : x2;
            a[2] = osel ? y1 : y0;
            a[3] = osel ? y3 : y2;
            #pragma unroll
            for (int dt = 0; dt < 8; ++dt) {
                const float2 bb = *(const float2*)&Vf[((ks*8+dt)*32 + lane)*2];
                mma8(o[dt], a, (const float*)&bb);
            }
        }
    }

    __syncthreads();
    l2[0] += __shfl_xor_sync(0xffffffffu, l2[0], 1);
    l2[0] += __shfl_xor_sync(0xffffffffu, l2[0], 2);
    l2[1] += __shfl_xor_sync(0xffffffffu, l2[1], 1);
    l2[1] += __shfl_xor_sync(0xffffffffu, l2[1], 2);

    float* sO = sm + 8192;
    {
        const float* xg = g_xh + (hb*NS + bx*128)*ND;
        #pragma unroll
        for (int r = 0; r < 2; ++r) {
            const float inv = 1.0f / l2[r];
            const int row = rA + 8*r;
            float psum = 0.f, psq = 0.f;
            #pragma unroll
            for (int dt = 0; dt < 8; ++dt) {
                const int col = dt*8 + t4*2;
                const float2 xr = *(const float2*)&xg[row*64 + col];
                const float v0 = o[dt][2*r]*inv + xr.x;
                const float v1 = o[dt][2*r+1]*inv + xr.y;
                *(float2*)&sO[row*PADP + col] = make_float2(v0, v1);
                psum += v0 + v1;
                psq  += v0*v0 + v1*v1;
            }
            psum += __shfl_xor_sync(0xffffffffu, psum, 1);
            psum += __shfl_xor_sync(0xffffffffu, psum, 2);
            psq  += __shfl_xor_sync(0xffffffffu, psq, 1);
            psq  += __shfl_xor_sync(0xffffffffu, psq, 2);
            if (t4 == 0) {
                const int si = hb*NS + bx*128 + row;
                g_psum[si] = psum;
                g_psq [si] = psq;
            }
        }
    }
    __syncthreads();
    {
        float* yg = g_y + (size_t)b*NE*NS + (size_t)(h*64)*NS + bx*128;
        for (int idx = tid; idx < 64*128; idx += 256) {
            const int d = idx >> 7, si = idx & 127;
            yg[d*NS + si] = sO[si*PADP + d];
        }
    }
}

// ---------------- kernel 3a: reduce head partials -> mu, rs per (b,s) -----------
__global__ __launch_bounds__(256) void k_stats()
{
    const int idx = blockIdx.x*256 + threadIdx.x;
    const int b = idx >> 10, s = idx & 1023;
    float ts = 0.f, tq = 0.f;
    #pragma unroll
    for (int h = 0; h < NH; ++h) {
        const int o = (h*NB + b)*NS + s;
        ts += g_psum[o];
        tq += g_psq [o];
    }
    const float mu = ts * (1.0f/1024.0f);
    const float var = tq * (1.0f/1024.0f) - mu*mu;
    g_mu[idx] = mu;
    g_rs[idx] = rsqrtf(var + 1e-5f);
}

// ---------------- kernel 3b: single-pass normalize (float4 over s) --------------
__global__ __launch_bounds__(256) void k_ln(const float* __restrict__ gamma,
                                            const float* __restrict__ beta,
                                            float* __restrict__ out)
{
    const int fi = (blockIdx.x*256 + threadIdx.x) * 4;
    const int s4 = fi & 1023, e = (fi >> 10) & 1023, b = fi >> 20;
    const float4 yv = *(const float4*)&g_y[fi];
    const float4 mu = *(const float4*)&g_mu[(b << 10) + s4];
    const float4 rs = *(const float4*)&g_rs[(b << 10) + s4];
    const float ga = __ldg(&gamma[e]), be = __ldg(&beta[e]);
    float4 ov;
    ov.x = (yv.x - mu.x)*rs.x*ga + be;
    ov.y = (yv.y - mu.y)*rs.y*ga + be;
    ov.z = (yv.z - mu.z)*rs.z*ga + be;
    ov.w = (yv.w - mu.w)*rs.w*ga + be;
    *(float4*)&out[fi] = ov;
}

// ---------------- launcher ----------------
extern "C" void kernel_launch(void* const* d_in, const int* in_sizes, int n_in,
                              void* d_out, int out_size)
{
    (void)in_sizes; (void)n_in; (void)out_size;
    const float* x   = (const float*)d_in[0];
    const float* Wq1 = (const float*)d_in[1];  const float* bq1 = (const float*)d_in[2];
    const float* Wq2 = (const float*)d_in[3];  const float* bq2 = (const float*)d_in[4];
    const float* Wk1 = (const float*)d_in[5];  const float* bk1 = (const float*)d_in[6];
    const float* Wk2 = (const float*)d_in[7];  const float* bk2 = (const float*)d_in[8];
    const float* Wv1 = (const float*)d_in[9];  const float* bv1 = (const float*)d_in[10];
    const float* Wv2 = (const float*)d_in[11]; const float* bv2 = (const float*)d_in[12];
    const float* gamma = (const float*)d_in[13];
    const float* beta  = (const float*)d_in[14];
    float* out = (float*)d_out;

    const int smem1 = SMEM1_FLOATS * (int)sizeof(float);
    const int smem2 = SMEM2_FLOATS * (int)sizeof(float);
    cudaFuncSetAttribute(k_qkv,  cudaFuncAttributeMaxDynamicSharedMemorySize, smem1);
    cudaFuncSetAttribute(k_attn, cudaFuncAttributeMaxDynamicSharedMemorySize, smem2);

    k_pe<<<NH*(ND/2)*NS/256, 256>>>();

    dim3 g1(NS/64, NB, NH);
    k_qkv<<<g1, 256, smem1>>>(x, Wq1, bq1, Wq2, bq2, Wk1, bk1, Wk2, bk2, Wv1, bv1, Wv2, bv2);

    dim3 g2(NS/128, NB, NH);
    k_attn<<<g2, 256, smem2>>>();

    k_stats<<<NB*NS/256, 256>>>();
    k_ln<<<NB*NE*NS/1024, 256>>>(gamma, beta, out);
}

// round 14
// speedup vs baseline: 1.0949x; 1.0949x over previous
#include <cuda_runtime.h>
#include <math.h>
#include <stdint.h>

#define NB 8
#define NH 16
#define ND 64
#define NS 1024
#define NE 1024
#define PADP 68   // row stride: 68 % 32 == 4 -> conflict-free row-set accesses
#define PADO 66   // output staging stride: even (float2-aligned), 2-way on transposed read

// ---------------- scratch ----------------
__device__ float g_pe[NH*ND*NS];     // (h,d,s) positional encoding
__device__ float g_xh[NH*NB*NS*ND];  // (h,b,s,d) pos-encoded input (residual), fp32
__device__ float g_q [NH*NB*NS*ND];  // A-frag layout per 128-row tile, scale folded
__device__ float g_k [NH*NB*NS*ND];  // B-frag layout per 64-row chunk
__device__ float g_v [NH*NB*NS*ND];  // B-frag (V role) layout per 64-row chunk
__device__ float g_y [NB*NE*NS];     // (b,e,s) pre-layernorm
__device__ float g_psum[NH*NB*NS];   // per-head partial sum of y over its 64 dims
__device__ float g_psq [NH*NB*NS];   // per-head partial sum of y^2
__device__ float g_mu[NB*NS];        // layernorm mean
__device__ float g_rs[NB*NS];        // layernorm rsqrt(var+eps)

// ---------------- helpers ----------------
__device__ __forceinline__ float ftanh(float x) {
    const float e = __expf(2.0f * x);
    return 1.0f - __fdividef(2.0f, e + 1.0f);
}
__device__ __forceinline__ void mma8(float* c, const float* a, const float* b) {
    asm volatile(
        "mma.sync.aligned.m16n8k8.row.col.f32.tf32.tf32.f32 "
        "{%0,%1,%2,%3}, {%4,%5,%6,%7}, {%8,%9}, {%0,%1,%2,%3};\n"
        : "+f"(c[0]), "+f"(c[1]), "+f"(c[2]), "+f"(c[3])
        : "r"(__float_as_uint(a[0])), "r"(__float_as_uint(a[1])),
          "r"(__float_as_uint(a[2])), "r"(__float_as_uint(a[3])),
          "r"(__float_as_uint(b[0])), "r"(__float_as_uint(b[1])));
}
__device__ __forceinline__ uint32_t su(const void* p) {
    return (uint32_t)__cvta_generic_to_shared(p);
}
__device__ __forceinline__ void cp16(uint32_t s, const void* g) {
    asm volatile("cp.async.cg.shared.global [%0], [%1], 16;\n" :: "r"(s), "l"(g));
}
__device__ __forceinline__ void cp4(uint32_t s, const void* g) {
    asm volatile("cp.async.ca.shared.global [%0], [%1], 4;\n" :: "r"(s), "l"(g));
}
#define CP_COMMIT asm volatile("cp.async.commit_group;\n" ::: "memory")
#define CP_WAIT0  asm volatile("cp.async.wait_group 0;\n" ::: "memory")
#define PAIR_BAR(rw) asm volatile("bar.sync %0, 64;" :: "r"((rw)+1) : "memory")

// ---------------- kernel 0: positional encoding table, (h,d,s) layout ------------
__global__ __launch_bounds__(256) void k_pe()
{
    const int idx = blockIdx.x*256 + threadIdx.x;   // over NH*(ND/2)*NS
    const int h = idx >> 15;
    const int m = (idx >> 10) & 31;
    const int s = idx & 1023;
    const int l = h*64 + (s >> 4);
    const int eh = ((s & 15) << 5) | m;
    const float freq = __expf((float)eh * (-2.0f*9.210340371976184f/1024.0f));
    float sv, cv;
    sincosf((float)l * freq, &sv, &cv);
    const int base = h*65536 + (m << 11) + s;
    g_pe[base]        = sv;
    g_pe[base + 1024] = cv;
}

// ---------------- kernel 1: posenc-add + QKV MLPs (512 threads, nt-split) --------
// smem: sXHf[8192] | sZ[128*68] | sWf0[4096] | sWf1[4096] = 98KB
#define SMEM1_FLOATS (8192 + 128*PADP + 4096 + 4096)

__device__ __forceinline__ void wfetch(uint32_t dstu, const float* __restrict__ W, int tid)
{
    #pragma unroll
    for (int i = 0; i < 8; ++i) {
        const int fi = tid + i*512;
        const int hi = fi & 1, ln = (fi >> 1) & 31, ks = (fi >> 6) & 7, nt = fi >> 9;
        const int g8 = ln >> 2, tt = ln & 3;
        cp4(dstu + fi*4, W + (ks*8 + tt + 4*hi)*64 + nt*8 + g8);
    }
}

// layer 1: A from sXHf (LDS.128 frags), nt-half per warp, out rows rA -> sZ
__device__ __forceinline__ void qkv_l1(const float* __restrict__ sXHf,
                                       const float* __restrict__ sWf,
                                       const float* __restrict__ biasg,
                                       float* __restrict__ sZ,
                                       int rw, int nh, int lane, int gid, int t4)
{
    const int rA = rw*16 + gid;
    float cc[4][4];
    #pragma unroll
    for (int nt = 0; nt < 4; ++nt) { cc[nt][0]=cc[nt][1]=cc[nt][2]=cc[nt][3]=0.f; }
    #pragma unroll
    for (int ks = 0; ks < 8; ++ks) {
        const float4 av = *(const float4*)&sXHf[((rw*8+ks)*32 + lane)*4];
        #pragma unroll
        for (int nt = 0; nt < 4; ++nt) {
            const float2 bb = *(const float2*)&sWf[(((nh*4+nt)*8+ks)*32 + lane)*2];
            mma8(cc[nt], (const float*)&av, (const float*)&bb);
        }
    }
    #pragma unroll
    for (int nt = 0; nt < 4; ++nt) {
        const int col = (nh*4+nt)*8 + t4*2;
        const float2 bv = *(const float2*)&biasg[col];
        #pragma unroll
        for (int r = 0; r < 2; ++r) {
            const int row = rA + 8*r;
            *(float2*)&sZ[row*PADP + col] =
                make_float2(ftanh(cc[nt][2*r] + bv.x), ftanh(cc[nt][2*r+1] + bv.y));
        }
    }
    PAIR_BAR(rw);   // pair (rw, nh=0/1) wrote both col halves of rows rA
}

// layer 2: A scalar from sZ (all ks), nt-half per warp, overwrite sZ rows rA
__device__ __forceinline__ void qkv_l2(float* __restrict__ sZ,
                                       const float* __restrict__ sWf,
                                       const float* __restrict__ biasg,
                                       int rw, int nh, int lane, int gid, int t4)
{
    const int rA = rw*16 + gid;
    float cc[4][4];
    #pragma unroll
    for (int nt = 0; nt < 4; ++nt) { cc[nt][0]=cc[nt][1]=cc[nt][2]=cc[nt][3]=0.f; }
    #pragma unroll
    for (int ks = 0; ks < 8; ++ks) {
        const int ac = ks*8 + t4;
        float a[4];
        a[0] = sZ[rA*PADP + ac];
        a[1] = sZ[(rA+8)*PADP + ac];
        a[2] = sZ[rA*PADP + ac + 4];
        a[3] = sZ[(rA+8)*PADP + ac + 4];
        #pragma unroll
        for (int nt = 0; nt < 4; ++nt) {
            const float2 bb = *(const float2*)&sWf[(((nh*4+nt)*8+ks)*32 + lane)*2];
            mma8(cc[nt], a, (const float*)&bb);
        }
    }
    PAIR_BAR(rw);   // both pair warps done reading rows rA before overwrite
    #pragma unroll
    for (int nt = 0; nt < 4; ++nt) {
        const int col = (nh*4+nt)*8 + t4*2;
        const float2 bv = *(const float2*)&biasg[col];
        #pragma unroll
        for (int r = 0; r < 2; ++r) {
            const int row = rA + 8*r;
            *(float2*)&sZ[row*PADP + col] =
                make_float2(ftanh(cc[nt][2*r] + bv.x), ftanh(cc[nt][2*r+1] + bv.y));
        }
    }
}

__global__ __launch_bounds__(512, 2) void k_qkv(
    const float* __restrict__ x,
    const float* __restrict__ Wq1, const float* __restrict__ bq1,
    const float* __restrict__ Wq2, const float* __restrict__ bq2,
    const float* __restrict__ Wk1, const float* __restrict__ bk1,
    const float* __restrict__ Wk2, const float* __restrict__ bk2,
    const float* __restrict__ Wv1, const float* __restrict__ bv1,
    const float* __restrict__ Wv2, const float* __restrict__ bv2)
{
    extern __shared__ float sm[];
    float* sXHf = sm;                        // [8192]
    float* sZ   = sXHf + 8192;               // [128*68]
    float* sWfA = sZ + 128*PADP;             // [4096]
    float* sWfB = sWfA + 4096;               // [4096]

    const int tid = threadIdx.x;
    const int lane = tid & 31, wid = tid >> 5;
    const int gid = lane >> 2, t4 = lane & 3;
    const int rw = wid & 7, nh = wid >> 3;
    const int h = blockIdx.z, b = blockIdx.y, bx = blockIdx.x;
    const int s0 = bx * 128;
    const int hb = h*NB + b;

    const float* Wl[6] = {Wq1, Wq2, Wk1, Wk2, Wv1, Wv2};
    const float* Bl[6] = {bq1, bq2, bk1, bk2, bv1, bv2};

    // prefetch W0 directly into frag layout; overlaps posenc work below
    wfetch(su(sWfA), Wl[0] + h*4096, tid);
    CP_COMMIT;

    // xh = x + pe (table lookup), into sZ
    for (int idx = tid; idx < 128*64; idx += 512) {
        const int d = idx >> 7, si = idx & 127;
        const int s = s0 + si;
        sZ[si*PADP + d] = x[(b*NE + (h*64 + d))*NS + s] + g_pe[h*65536 + (d << 10) + s];
    }
    __syncthreads();
    {   // residual persist + xh A-frag build (vectorized quad)
        float* dst = g_xh + (hb*NS + s0)*ND;
        for (int idx = tid; idx < 128*16; idx += 512) {
            const int si = idx >> 4, d4 = (idx & 15) * 4;
            *(float4*)(dst + si*64 + d4) = *(float4*)&sZ[si*PADP + d4];
        }
        for (int f4 = tid*4; f4 < 8192; f4 += 2048) {
            const int w = f4 >> 10, ks = (f4 >> 7) & 7, ln = (f4 >> 2) & 31;
            const int g8 = ln >> 2, tt = ln & 3;
            const int row0 = w*16 + g8, col0 = ks*8 + tt;
            float4 v;
            v.x = sZ[row0*PADP + col0];
            v.y = sZ[(row0+8)*PADP + col0];
            v.z = sZ[row0*PADP + col0 + 4];
            v.w = sZ[(row0+8)*PADP + col0 + 4];
            *(float4*)&sXHf[f4] = v;
        }
    }
    CP_WAIT0;
    __syncthreads();   // W0 visible; sXHf build complete before l1

    float* cur = sWfA;
    float* nxt = sWfB;

    #pragma unroll 1
    for (int l = 0; l < 6; ++l) {
        if (l < 5) { wfetch(su(nxt), Wl[l+1] + h*4096, tid); CP_COMMIT; }
        if ((l & 1) == 0) {
            qkv_l1(sXHf, cur, Bl[l] + h*64, sZ, rw, nh, lane, gid, t4);
        } else {
            qkv_l2(sZ, cur, Bl[l] + h*64, rw, nh, lane, gid, t4);
            __syncthreads();   // sZ final before block-wide permute reads
            const int p = l >> 1;
            if (p == 0) {          // Q: A-frag tiles, scale folded (STG.128 quads)
                float* qb = g_q + (hb*8 + bx)*8192;
                for (int f4 = tid*4; f4 < 8192; f4 += 2048) {
                    const int w = f4 >> 10, ks = (f4 >> 7) & 7, ln = (f4 >> 2) & 31;
                    const int g8 = ln >> 2, tt = ln & 3;
                    const int row0 = w*16 + g8, col0 = ks*8 + tt;
                    float4 v;
                    v.x = 0.03125f * sZ[row0*PADP + col0];
                    v.y = 0.03125f * sZ[(row0+8)*PADP + col0];
                    v.z = 0.03125f * sZ[row0*PADP + col0 + 4];
                    v.w = 0.03125f * sZ[(row0+8)*PADP + col0 + 4];
                    *(float4*)&qb[f4] = v;
                }
            } else if (p == 1) {   // K: B-frag chunks (2x LDS.64 + STG.128)
                float* kb = g_k + (hb*16 + bx*2)*4096;
                for (int i4 = tid*4; i4 < 8192; i4 += 2048) {
                    const int cl = i4 >> 12, f = i4 & 4095;
                    const int ln = (f >> 1) & 31, g8 = ln >> 2, tt = ln & 3;  // tt even
                    const int ks = (f >> 6) & 7, nt = f >> 9;
                    const int row = cl*64 + nt*8 + g8;
                    const float2 a0 = *(const float2*)&sZ[row*PADP + ks*8 + tt];
                    const float2 a4 = *(const float2*)&sZ[row*PADP + ks*8 + tt + 4];
                    *(float4*)&kb[i4] = make_float4(a0.x, a4.x, a0.y, a4.y);
                }
            } else {               // V: k=j, n=d frag chunks (4x LDS.32 + STG.128)
                float* vb = g_v + (hb*16 + bx*2)*4096;
                for (int i4 = tid*4; i4 < 8192; i4 += 2048) {
                    const int cl = i4 >> 12, f = i4 & 4095;
                    const int ln = (f >> 1) & 31, g8 = ln >> 2, tt = ln & 3;  // tt even
                    const int dt = (f >> 6) & 7, ksv = f >> 9;
                    const int row = cl*64 + ksv*8 + tt;
                    const int col = dt*8 + g8;
                    float4 v;
                    v.x = sZ[row*PADP + col];
                    v.y = sZ[(row+4)*PADP + col];
                    v.z = sZ[(row+1)*PADP + col];
                    v.w = sZ[(row+5)*PADP + col];
                    *(float4*)&vb[i4] = v;
                }
            }
        }
        if (l < 5) { CP_WAIT0; }
        __syncthreads();   // next W visible; sZ free for reuse
        float* t = cur; cur = nxt; nxt = t;
    }
}

// ---------------- kernel 2: flash attention + residual + LN partial stats ----------
// smem: sQf[8192] | buf0 K/V [8192] | buf1 K/V [8192] = 96KB
#define SMEM2_FLOATS (8192 + 8192 + 8192)

__global__ __launch_bounds__(256, 2) void k_attn()
{
    extern __shared__ float sm[];
    float* sQf  = sm;
    float* buf0 = sm + 8192;
    float* buf1 = sm + 16384;
    const uint32_t b0u = su(buf0), b1u = su(buf1), qfu = su(sQf);

    const int tid = threadIdx.x;
    const int lane = tid & 31, wid = tid >> 5;
    const int gid = lane >> 2, t4 = lane & 3;
    const int rA = wid*16 + gid;

    const int h = blockIdx.z, b = blockIdx.y, bx = blockIdx.x;
    const int hb = h*NB + b;
    const float* qt = g_q + (hb*8 + bx)*8192;
    const float* kb = g_k + hb*16*4096;
    const float* vb = g_v + hb*16*4096;

    #pragma unroll
    for (int i = 0; i < 8; ++i)
        cp16(qfu + (tid + i*256)*16, qt + (tid + i*256)*4);
    #pragma unroll
    for (int i = 0; i < 4; ++i) {
        cp16(b0u + (tid + i*256)*16,         kb + (tid + i*256)*4);
        cp16(b0u + 16384 + (tid + i*256)*16, vb + (tid + i*256)*4);
    }
    CP_COMMIT;

    float l2[2] = {0.f, 0.f};
    float o[8][4];
    #pragma unroll
    for (int nt = 0; nt < 8; ++nt) { o[nt][0]=o[nt][1]=o[nt][2]=o[nt][3]=0.f; }

    const int qsrc1 = (lane & ~3) | (t4 >> 1);
    const int qsrc2 = qsrc1 + 2;
    const bool osel = (t4 & 1);

    #pragma unroll 1
    for (int kt = 0; kt < 16; ++kt) {
        CP_WAIT0;
        __syncthreads();
        if (kt < 15) {
            const uint32_t bu = ((kt+1) & 1) ? b1u : b0u;
            const float* ksrc = kb + (kt+1)*4096;
            const float* vsrc = vb + (kt+1)*4096;
            #pragma unroll
            for (int i = 0; i < 4; ++i) {
                cp16(bu + (tid + i*256)*16,         ksrc + (tid + i*256)*4);
                cp16(bu + 16384 + (tid + i*256)*16, vsrc + (tid + i*256)*4);
            }
            CP_COMMIT;
        }
        const float* Kf = (kt & 1) ? buf1 : buf0;
        const float* Vf = Kf + 4096;

        float sc[8][4];
        #pragma unroll
        for (int nt = 0; nt < 8; ++nt) { sc[nt][0]=sc[nt][1]=sc[nt][2]=sc[nt][3]=0.f; }
        #pragma unroll
        for (int ks = 0; ks < 8; ++ks) {
            const float4 av = *(const float4*)&sQf[((wid*8+ks)*32 + lane)*4];
            #pragma unroll
            for (int nt = 0; nt < 8; ++nt) {
                const float2 bb = *(const float2*)&Kf[((nt*8+ks)*32 + lane)*2];
                mma8(sc[nt], (const float*)&av, (const float*)&bb);
            }
        }

        #pragma unroll
        for (int nt = 0; nt < 8; ++nt) {
            sc[nt][0] = __expf(sc[nt][0]);
            sc[nt][1] = __expf(sc[nt][1]);
            sc[nt][2] = __expf(sc[nt][2]);
            sc[nt][3] = __expf(sc[nt][3]);
            l2[0] += sc[nt][0] + sc[nt][1];
            l2[1] += sc[nt][2] + sc[nt][3];
        }

        #pragma unroll
        for (int ks = 0; ks < 8; ++ks) {
            const float x0 = __shfl_sync(0xffffffffu, sc[ks][0], qsrc1);
            const float x1 = __shfl_sync(0xffffffffu, sc[ks][1], qsrc1);
            const float x2 = __shfl_sync(0xffffffffu, sc[ks][2], qsrc1);
            const float x3 = __shfl_sync(0xffffffffu, sc[ks][3], qsrc1);
            const float y0 = __shfl_sync(0xffffffffu, sc[ks][0], qsrc2);
            const float y1 = __shfl_sync(0xffffffffu, sc[ks][1], qsrc2);
            const float y2 = __shfl_sync(0xffffffffu, sc[ks][2], qsrc2);
            const float y3 = __shfl_sync(0xffffffffu, sc[ks][3], qsrc2);
            float a[4];
            a[0] = osel ? x1 : x0;
            a[1] = osel ? x3 : x2;
            a[2] = osel ? y1 : y0;
            a[3] = osel ? y3 : y2;
            #pragma unroll
            for (int dt = 0; dt < 8; ++dt) {
                const float2 bb = *(const float2*)&Vf[((ks*8+dt)*32 + lane)*2];
                mma8(o[dt], a, (const float*)&bb);
            }
        }
    }

    __syncthreads();
    l2[0] += __shfl_xor_sync(0xffffffffu, l2[0], 1);
    l2[0] += __shfl_xor_sync(0xffffffffu, l2[0], 2);
    l2[1] += __shfl_xor_sync(0xffffffffu, l2[1], 1);
    l2[1] += __shfl_xor_sync(0xffffffffu, l2[1], 2);

    float* sO = sm + 8192;   // [128*66] fits in 16384 floats
    {
        const float* xg = g_xh + (hb*NS + bx*128)*ND;
        #pragma unroll
        for (int r = 0; r < 2; ++r) {
            const float inv = 1.0f / l2[r];
            const int row = rA + 8*r;
            float psum = 0.f, psq = 0.f;
            #pragma unroll
            for (int dt = 0; dt < 8; ++dt) {
                const int col = dt*8 + t4*2;
                const float2 xr = *(const float2*)&xg[row*64 + col];
                const float v0 = o[dt][2*r]*inv + xr.x;
                const float v1 = o[dt][2*r+1]*inv + xr.y;
                *(float2*)&sO[row*PADO + col] = make_float2(v0, v1);
                psum += v0 + v1;
                psq  += v0*v0 + v1*v1;
            }
            psum += __shfl_xor_sync(0xffffffffu, psum, 1);
            psum += __shfl_xor_sync(0xffffffffu, psum, 2);
            psq  += __shfl_xor_sync(0xffffffffu, psq, 1);
            psq  += __shfl_xor_sync(0xffffffffu, psq, 2);
            if (t4 == 0) {
                const int si = hb*NS + bx*128 + row;
                g_psum[si] = psum;
                g_psq [si] = psq;
            }
        }
    }
    __syncthreads();
    {
        float* yg = g_y + (size_t)b*NE*NS + (size_t)(h*64)*NS + bx*128;
        for (int idx = tid; idx < 64*128; idx += 256) {
            const int d = idx >> 7, si = idx & 127;
            yg[d*NS + si] = sO[si*PADO + d];
        }
    }
}

// ---------------- kernel 3a: reduce head partials -> mu, rs per (b,s) -----------
__global__ __launch_bounds__(256) void k_stats()
{
    const int idx = blockIdx.x*256 + threadIdx.x;
    const int b = idx >> 10, s = idx & 1023;
    float ts = 0.f, tq = 0.f;
    #pragma unroll
    for (int h = 0; h < NH; ++h) {
        const int o = (h*NB + b)*NS + s;
        ts += g_psum[o];
        tq += g_psq [o];
    }
    const float mu = ts * (1.0f/1024.0f);
    const float var = tq * (1.0f/1024.0f) - mu*mu;
    g_mu[idx] = mu;
    g_rs[idx] = rsqrtf(var + 1e-5f);
}

// ---------------- kernel 3b: single-pass normalize (float4 over s) --------------
__global__ __launch_bounds__(256) void k_ln(const float* __restrict__ gamma,
                                            const float* __restrict__ beta,
                                            float* __restrict__ out)
{
    const int fi = (blockIdx.x*256 + threadIdx.x) * 4;
    const int s4 = fi & 1023, e = (fi >> 10) & 1023, b = fi >> 20;
    const float4 yv = *(const float4*)&g_y[fi];
    const float4 mu = *(const float4*)&g_mu[(b << 10) + s4];
    const float4 rs = *(const float4*)&g_rs[(b << 10) + s4];
    const float ga = __ldg(&gamma[e]), be = __ldg(&beta[e]);
    float4 ov;
    ov.x = (yv.x - mu.x)*rs.x*ga + be;
    ov.y = (yv.y - mu.y)*rs.y*ga + be;
    ov.z = (yv.z - mu.z)*rs.z*ga + be;
    ov.w = (yv.w - mu.w)*rs.w*ga + be;
    *(float4*)&out[fi] = ov;
}

// ---------------- launcher ----------------
extern "C" void kernel_launch(void* const* d_in, const int* in_sizes, int n_in,
                              void* d_out, int out_size)
{
    (void)in_sizes; (void)n_in; (void)out_size;
    const float* x   = (const float*)d_in[0];
    const float* Wq1 = (const float*)d_in[1];  const float* bq1 = (const float*)d_in[2];
    const float* Wq2 = (const float*)d_in[3];  const float* bq2 = (const float*)d_in[4];
    const float* Wk1 = (const float*)d_in[5];  const float* bk1 = (const float*)d_in[6];
    const float* Wk2 = (const float*)d_in[7];  const float* bk2 = (const float*)d_in[8];
    const float* Wv1 = (const float*)d_in[9];  const float* bv1 = (const float*)d_in[10];
    const float* Wv2 = (const float*)d_in[11]; const float* bv2 = (const float*)d_in[12];
    const float* gamma = (const float*)d_in[13];
    const float* beta  = (const float*)d_in[14];
    float* out = (float*)d_out;

    const int smem1 = SMEM1_FLOATS * (int)sizeof(float);
    const int smem2 = SMEM2_FLOATS * (int)sizeof(float);
    cudaFuncSetAttribute(k_qkv,  cudaFuncAttributeMaxDynamicSharedMemorySize, smem1);
    cudaFuncSetAttribute(k_attn, cudaFuncAttributeMaxDynamicSharedMemorySize, smem2);

    k_pe<<<NH*(ND/2)*NS/256, 256>>>();

    dim3 g1(NS/128, NB, NH);
    k_qkv<<<g1, 512, smem1>>>(x, Wq1, bq1, Wq2, bq2, Wk1, bk1, Wk2, bk2, Wv1, bv1, Wv2, bv2);

    dim3 g2(NS/128, NB, NH);
    k_attn<<<g2, 256, smem2>>>();

    k_stats<<<NB*NS/256, 256>>>();
    k_ln<<<NB*NE*NS/1024, 256>>>(gamma, beta, out);
}